// round 5
// baseline (speedup 1.0000x reference)
#include <cuda_runtime.h>

// ---------------------------------------------------------------------------
#define P_ELEMS (96*96*96)          // 884736 points per sample
#define NSAMP   4
#define NB      32
#define NBINS2  (NB*NB)
#define CPS     37                  // CTAs per sample
#define NCTA    (CPS*NSAMP)         // 148 = one full wave, 1 CTA/SM

// C = 2048/961 = 2.1311134235 ; exp2 form: C*log2(e)
#define EXP2_C   3.0745468f
#define G_QTR    0.58697259f        // exp(-0.25*C)
#define G_225    8.2709087e-3f      // exp(-2.25*C)
#define EPS      1e-10f

// ---------------------------------------------------------------------------
// Device scratch (no allocations allowed)
__device__ float    g_pmnT[NCTA], g_pmxT[NCTA], g_pmnS[NCTA], g_pmxS[NCTA];
__device__ float    g_hist[NSAMP*NBINS2];
__device__ unsigned g_bar0 = 0;     // phase-1 barrier arrivals
__device__ unsigned g_bar1 = 0;     // completion arrivals (last CTA finalizes)

// ---------------------------------------------------------------------------
// 4-wide Gaussian window via ratio chain: 3 EX2 per axis.
__device__ __forceinline__ void gauss4(float f, int& i0, float w[4]) {
    i0 = min(max(__float2int_rd(f) - 1, 0), NB - 4);
    float m  = f - (float)i0 - 1.5f;
    float E  = exp2f(-EXP2_C * m * m);
    float R  = exp2f(-EXP2_C * m);
    float Ri = exp2f( EXP2_C * m);
    float a = E * G_QTR;
    w[1] = a * R;
    w[2] = a * Ri;
    float b = E * G_225;
    w[0] = b * (R * R * R);
    w[3] = b * (Ri * Ri * Ri);
}

// ---------------------------------------------------------------------------
// Single fused persistent kernel: minmax -> grid barrier -> histogram ->
// merge -> last CTA finalizes. 148 CTAs x 1024 thr, 128KB smem, 1 CTA/SM.
__global__ void __launch_bounds__(1024, 1)
k_all(const float* __restrict__ tar, const float* __restrict__ src,
      float* __restrict__ out) {
    extern __shared__ float sh[];           // [NBINS2][32] lane-interleaved hist
    const int bx  = blockIdx.x;
    const int b   = bx / CPS;               // sample
    const int sl  = bx % CPS;               // slice within sample
    const int tid = threadIdx.x;
    const int lane = tid & 31, wrp = tid >> 5;

    // ---- zero global hist (first 4 CTAs) and shared hist ----
    if (bx < NSAMP) g_hist[bx * NBINS2 + tid] = 0.0f;
    {
        float4* z4 = (float4*)sh;
        #pragma unroll
        for (int i = tid; i < NBINS2 * 32 / 4; i += 1024)
            z4[i] = make_float4(0.f, 0.f, 0.f, 0.f);
    }

    // ---- Phase 1: minmax partials over this CTA's slice ----
    const float4* t4 = (const float4*)(tar + (size_t)b * P_ELEMS);
    const float4* s4 = (const float4*)(src + (size_t)b * P_ELEMS);
    const int n4 = P_ELEMS / 4;

    float mnT = 1e30f, mxT = -1e30f, mnS = 1e30f, mxS = -1e30f;
    for (int i = sl * 1024 + tid; i < n4; i += CPS * 1024) {
        float4 v = t4[i];
        mnT = fminf(mnT, fminf(fminf(v.x, v.y), fminf(v.z, v.w)));
        mxT = fmaxf(mxT, fmaxf(fmaxf(v.x, v.y), fmaxf(v.z, v.w)));
        float4 u = s4[i];
        mnS = fminf(mnS, fminf(fminf(u.x, u.y), fminf(u.z, u.w)));
        mxS = fmaxf(mxS, fmaxf(fmaxf(u.x, u.y), fmaxf(u.z, u.w)));
    }
    #pragma unroll
    for (int o = 16; o > 0; o >>= 1) {
        mnT = fminf(mnT, __shfl_xor_sync(0xffffffffu, mnT, o));
        mxT = fmaxf(mxT, __shfl_xor_sync(0xffffffffu, mxT, o));
        mnS = fminf(mnS, __shfl_xor_sync(0xffffffffu, mnS, o));
        mxS = fmaxf(mxS, __shfl_xor_sync(0xffffffffu, mxS, o));
    }
    __shared__ float sm[4][32];
    __shared__ float lim[4];
    if (lane == 0) {
        sm[0][wrp] = mnT; sm[1][wrp] = mxT; sm[2][wrp] = mnS; sm[3][wrp] = mxS;
    }
    __syncthreads();
    if (tid == 0) {
        float a = sm[0][0], c = sm[1][0], e = sm[2][0], f = sm[3][0];
        #pragma unroll
        for (int i = 1; i < 32; i++) {
            a = fminf(a, sm[0][i]); c = fmaxf(c, sm[1][i]);
            e = fminf(e, sm[2][i]); f = fmaxf(f, sm[3][i]);
        }
        g_pmnT[bx] = a; g_pmxT[bx] = c; g_pmnS[bx] = e; g_pmxS[bx] = f;
        // release + arrive
        __threadfence();
        atomicAdd(&g_bar0, 1u);
        while (*(volatile unsigned*)&g_bar0 < NCTA) { }
    }
    __syncthreads();

    // ---- reduce the 37 partials for this sample (L2 reads, bypass L1) ----
    if (tid < 4) {
        const float* arr = (tid == 0) ? g_pmnT : (tid == 1) ? g_pmxT :
                           (tid == 2) ? g_pmnS : g_pmxS;
        bool ismin = (tid & 1) == 0;
        float r = __ldcg(&arr[b * CPS]);
        #pragma unroll
        for (int i = 1; i < CPS; i++) {
            float v = __ldcg(&arr[b * CPS + i]);
            r = ismin ? fminf(r, v) : fmaxf(r, v);
        }
        lim[tid] = r;
    }
    __syncthreads();

    const float mnTf = lim[0], mxTf = lim[1], mnSf = lim[2], mxSf = lim[3];
    const float scT = 31.0f / (mxTf - mnTf + 1e-12f);
    const float scS = 31.0f / (mxSf - mnSf + 1e-12f);

    // ---- Phase 2: joint histogram, 4x4 window, conflict-free lane-ATOMS ----
    float* hb = sh + lane;                  // this lane's copy base
    for (int p = sl * 1024 + tid; p < n4; p += CPS * 1024) {
        float4 tv = t4[p];
        float4 sv = s4[p];
        float tf[4] = {tv.x, tv.y, tv.z, tv.w};
        float sf[4] = {sv.x, sv.y, sv.z, sv.w};
        #pragma unroll
        for (int q = 0; q < 4; q++) {
            float ft = (tf[q] - mnTf) * scT;
            float fs = (sf[q] - mnSf) * scS;
            int it0, js0;
            float wt[4], ws[4];
            gauss4(ft, it0, wt);
            gauss4(fs, js0, ws);
            float* base = hb + ((it0 * NB + js0) << 5);
            #pragma unroll
            for (int k = 0; k < 4; k++) {
                float w = wt[k];
                #pragma unroll
                for (int l = 0; l < 4; l++)
                    atomicAdd(base + (((k * NB) + l) << 5), w * ws[l]);
            }
        }
    }
    __syncthreads();

    // ---- merge 32 lane copies per bin into g_hist (rotated, conflict-free) ----
    for (int bin = tid; bin < NBINS2; bin += 1024) {
        const float* c = sh + (bin << 5);
        float s = 0.0f;
        #pragma unroll
        for (int i = 0; i < 32; i++) s += c[(lane + i) & 31];
        atomicAdd(&g_hist[b * NBINS2 + bin], s);
    }
    __threadfence();
    __syncthreads();

    // ---- completion arrive; last CTA finalizes ----
    __shared__ unsigned s_rank;
    if (tid == 0) s_rank = atomicAdd(&g_bar1, 1u);
    __syncthreads();
    if (s_rank != NCTA - 1) return;

    // last CTA: norm + entropies + loss (threads 0..127, warp w = sample w)
    if (tid < 128) {
        float (*smp)[33] = (float(*)[33])sh;        // [4*32][33] reuse
        __shared__ float part[4];
        const int w = tid >> 5, ln = tid & 31;

        float v[32];
        #pragma unroll
        for (int i = 0; i < 32; i++)
            v[i] = __ldcg(&g_hist[w * NBINS2 + i * NB + ln]);  // column 'ln'

        float cs = 0.0f;
        #pragma unroll
        for (int i = 0; i < 32; i++) cs += v[i];
        float norm = cs;
        #pragma unroll
        for (int o = 16; o > 0; o >>= 1) norm += __shfl_xor_sync(0xffffffffu, norm, o);
        float inv = __frcp_rn(norm);

        float ej = 0.0f;
        #pragma unroll
        for (int i = 0; i < 32; i++) {
            float p = v[i] * inv;
            smp[w * 32 + i][ln] = p;
            ej += p * __logf(p + EPS);
        }
        #pragma unroll
        for (int o = 16; o > 0; o >>= 1) ej += __shfl_xor_sync(0xffffffffu, ej, o);

        float qq = cs * inv;
        float es = qq * __logf(qq + EPS);
        #pragma unroll
        for (int o = 16; o > 0; o >>= 1) es += __shfl_xor_sync(0xffffffffu, es, o);

        __syncwarp();
        float r = 0.0f;
        #pragma unroll
        for (int j = 0; j < 32; j++) r += smp[w * 32 + ln][j];
        float et = r * __logf(r + EPS);
        #pragma unroll
        for (int o = 16; o > 0; o >>= 1) et += __shfl_xor_sync(0xffffffffu, et, o);

        if (ln == 0) part[w] = (et + es) / ej;
        __syncwarp();
        if (tid == 0) {
            out[0] = -(part[0] + part[1] + part[2] + part[3]) * 0.25f;
            // reset barriers for next graph replay (all CTAs already arrived)
            g_bar0 = 0u;
            g_bar1 = 0u;
        }
    }
}

// ---------------------------------------------------------------------------
extern "C" void kernel_launch(void* const* d_in, const int* in_sizes, int n_in,
                              void* d_out, int out_size) {
    const float* tar = (const float*)d_in[0];
    const float* src = (const float*)d_in[1];
    float* out = (float*)d_out;

    static bool attr_set = false;
    if (!attr_set) {
        cudaFuncSetAttribute(k_all, cudaFuncAttributeMaxDynamicSharedMemorySize,
                             NBINS2 * 32 * sizeof(float));
        attr_set = true;
    }

    k_all<<<NCTA, 1024, NBINS2 * 32 * sizeof(float)>>>(tar, src, out);
}

// round 6
// speedup vs baseline: 1.2000x; 1.2000x over previous
#include <cuda_runtime.h>

// ---------------------------------------------------------------------------
#define P_ELEMS (96*96*96)          // 884736 points per sample
#define NSAMP   4
#define NB      32
#define NBINS2  (NB*NB)
#define MM_CTAS 37                  // minmax CTAs per sample (37*4=148)

// C = 2048/961 = 2.1311134235 ; exp2 form: C*log2(e)
#define EXP2_C   3.0745468f
#define EXP2_2C  6.1490936f
#define G_QTR    0.58697259f        // exp(-0.25*C)
#define G_225    8.2709087e-3f      // exp(-2.25*C)
#define G_1      0.11870463f        // exp(-C)
#define EPS      1e-10f

// ---------------------------------------------------------------------------
// Device scratch (no allocations allowed)
__device__ float g_pmnT[NSAMP*MM_CTAS];
__device__ float g_pmxT[NSAMP*MM_CTAS];
__device__ float g_pmnS[NSAMP*MM_CTAS];
__device__ float g_pmxS[NSAMP*MM_CTAS];
__device__ float g_hist[NSAMP*NBINS2];

// ---------------------------------------------------------------------------
// Pass 1: per-CTA min/max partials. 1024 threads, 2-way strided unroll for MLP.
__global__ void __launch_bounds__(1024) k_pre(const float* __restrict__ tar,
                                              const float* __restrict__ src) {
    int b = blockIdx.y;
    if (b == 0) {
        int idx = blockIdx.x * 1024 + threadIdx.x;   // 37*1024 covers 4096
        if (idx < NSAMP * NBINS2) g_hist[idx] = 0.0f;
    }

    const float4* t4 = (const float4*)(tar + (size_t)b * P_ELEMS);
    const float4* s4 = (const float4*)(src + (size_t)b * P_ELEMS);
    const int n4 = P_ELEMS / 4;
    const int stride = MM_CTAS * 1024;

    float mnT = 1e30f, mxT = -1e30f, mnS = 1e30f, mxS = -1e30f;
    int i = blockIdx.x * 1024 + threadIdx.x;
    for (; i + stride < n4; i += 2 * stride) {
        float4 v0 = t4[i];
        float4 u0 = s4[i];
        float4 v1 = t4[i + stride];
        float4 u1 = s4[i + stride];
        mnT = fminf(mnT, fminf(fminf(fminf(v0.x, v0.y), fminf(v0.z, v0.w)),
                               fminf(fminf(v1.x, v1.y), fminf(v1.z, v1.w))));
        mxT = fmaxf(mxT, fmaxf(fmaxf(fmaxf(v0.x, v0.y), fmaxf(v0.z, v0.w)),
                               fmaxf(fmaxf(v1.x, v1.y), fmaxf(v1.z, v1.w))));
        mnS = fminf(mnS, fminf(fminf(fminf(u0.x, u0.y), fminf(u0.z, u0.w)),
                               fminf(fminf(u1.x, u1.y), fminf(u1.z, u1.w))));
        mxS = fmaxf(mxS, fmaxf(fmaxf(fmaxf(u0.x, u0.y), fmaxf(u0.z, u0.w)),
                               fmaxf(fmaxf(u1.x, u1.y), fmaxf(u1.z, u1.w))));
    }
    for (; i < n4; i += stride) {
        float4 v = t4[i];
        float4 u = s4[i];
        mnT = fminf(mnT, fminf(fminf(v.x, v.y), fminf(v.z, v.w)));
        mxT = fmaxf(mxT, fmaxf(fmaxf(v.x, v.y), fmaxf(v.z, v.w)));
        mnS = fminf(mnS, fminf(fminf(u.x, u.y), fminf(u.z, u.w)));
        mxS = fmaxf(mxS, fmaxf(fmaxf(u.x, u.y), fmaxf(u.z, u.w)));
    }
    #pragma unroll
    for (int o = 16; o > 0; o >>= 1) {
        mnT = fminf(mnT, __shfl_xor_sync(0xffffffffu, mnT, o));
        mxT = fmaxf(mxT, __shfl_xor_sync(0xffffffffu, mxT, o));
        mnS = fminf(mnS, __shfl_xor_sync(0xffffffffu, mnS, o));
        mxS = fmaxf(mxS, __shfl_xor_sync(0xffffffffu, mxS, o));
    }
    __shared__ float sm[4][32];
    int w = threadIdx.x >> 5;
    if ((threadIdx.x & 31) == 0) {
        sm[0][w] = mnT; sm[1][w] = mxT; sm[2][w] = mnS; sm[3][w] = mxS;
    }
    __syncthreads();
    if (threadIdx.x == 0) {
        float a = sm[0][0], c = sm[1][0], e = sm[2][0], f = sm[3][0];
        #pragma unroll
        for (int k = 1; k < 32; k++) {
            a = fminf(a, sm[0][k]); c = fmaxf(c, sm[1][k]);
            e = fminf(e, sm[2][k]); f = fmaxf(f, sm[3][k]);
        }
        int slot = b * MM_CTAS + blockIdx.x;
        g_pmnT[slot] = a; g_pmxT[slot] = c;
        g_pmnS[slot] = e; g_pmxS[slot] = f;
    }
}

// ---------------------------------------------------------------------------
// 4-wide Gaussian window (ratio chain, 3 EX2)
__device__ __forceinline__ void gauss4(float f, int& i0, float w[4]) {
    i0 = min(max(__float2int_rd(f) - 1, 0), NB - 4);
    float m  = f - (float)i0 - 1.5f;
    float E  = exp2f(-EXP2_C * m * m);
    float R  = exp2f(-EXP2_C * m);
    float Ri = exp2f( EXP2_C * m);
    float a = E * G_QTR;
    w[1] = a * R;
    w[2] = a * Ri;
    float b = E * G_225;
    w[0] = b * (R * R * R);
    w[3] = b * (Ri * Ri * Ri);
}

// 3-wide Gaussian window (ratio chain, 3 EX2). bins i0..i0+2, m = f-(i0+1).
// w[k] = exp(-C*(m-(k-1))^2) = E * G_1^{(k-1)^2} * exp(-2Cm)^{-(k-1)}
__device__ __forceinline__ void gauss3(float f, int& i0, float w[3]) {
    i0 = min(max(__float2int_rn(f) - 1, 0), NB - 3);
    float m  = f - (float)i0 - 1.0f;
    float E  = exp2f(-EXP2_C * m * m);
    float X  = exp2f(-EXP2_2C * m);      // exp(-2Cm)
    float Xi = exp2f( EXP2_2C * m);      // exp(+2Cm)
    w[1] = E;
    float a = E * G_1;
    w[0] = a * X;                         // d = m+1
    w[2] = a * Xi;                        // d = m-1
}

// ---------------------------------------------------------------------------
// Pass 2: joint histogram, 4(tar) x 3(src) truncated window -> 12 ATOMS/point.
// Lane-interleaved private copies (bank == lane, conflict-free ATOMS).
__global__ void __launch_bounds__(1024, 1) k_hist(const float* __restrict__ tar,
                                                  const float* __restrict__ src) {
    extern __shared__ float sh[];           // [NBINS2][32]
    const int b = blockIdx.y;

    float4* z4 = (float4*)sh;
    #pragma unroll
    for (int i = threadIdx.x; i < NBINS2 * 32 / 4; i += 1024)
        z4[i] = make_float4(0.f, 0.f, 0.f, 0.f);

    __shared__ float lim[4];
    if (threadIdx.x < 4) {
        const float* arr = (threadIdx.x == 0) ? g_pmnT :
                           (threadIdx.x == 1) ? g_pmxT :
                           (threadIdx.x == 2) ? g_pmnS : g_pmxS;
        bool ismin = (threadIdx.x & 1) == 0;
        float r = arr[b * MM_CTAS];
        #pragma unroll
        for (int i = 1; i < MM_CTAS; i++) {
            float v = arr[b * MM_CTAS + i];
            r = ismin ? fminf(r, v) : fmaxf(r, v);
        }
        lim[threadIdx.x] = r;
    }
    __syncthreads();

    const float mnT = lim[0], mxT = lim[1], mnS = lim[2], mxS = lim[3];
    const float scT = 31.0f / (mxT - mnT + 1e-12f);
    const float scS = 31.0f / (mxS - mnS + 1e-12f);

    const float4* t4 = (const float4*)(tar + (size_t)b * P_ELEMS);
    const float4* s4 = (const float4*)(src + (size_t)b * P_ELEMS);
    float* hb = sh + (threadIdx.x & 31);
    const int n4 = P_ELEMS / 4;

    for (int p = blockIdx.x * 1024 + threadIdx.x; p < n4; p += 37 * 1024) {
        float4 tv = t4[p];
        float4 sv = s4[p];
        float tf[4] = {tv.x, tv.y, tv.z, tv.w};
        float sf[4] = {sv.x, sv.y, sv.z, sv.w};
        #pragma unroll
        for (int q = 0; q < 4; q++) {
            float ft = (tf[q] - mnT) * scT;
            float fs = (sf[q] - mnS) * scS;
            int it0, js0;
            float wt[4], ws[3];
            gauss4(ft, it0, wt);
            gauss3(fs, js0, ws);

            float* base = hb + ((it0 * NB + js0) << 5);
            #pragma unroll
            for (int k = 0; k < 4; k++) {
                float w = wt[k];
                #pragma unroll
                for (int l = 0; l < 3; l++)
                    atomicAdd(base + (((k * NB) + l) << 5), w * ws[l]);
            }
        }
    }

    __syncthreads();
    // merge 32 lane copies per bin, rotated reads (conflict-free)
    const int lane = threadIdx.x & 31;
    {
        int bin = threadIdx.x;
        const float* c = sh + (bin << 5);
        float s = 0.0f;
        #pragma unroll
        for (int i = 0; i < 32; i++) s += c[(lane + i) & 31];
        atomicAdd(&g_hist[b * NBINS2 + bin], s);
    }
}

// ---------------------------------------------------------------------------
// Pass 3: norm + entropies + loss. 1 CTA, warp w = sample w.
__global__ void __launch_bounds__(128) k_final(float* __restrict__ out) {
    __shared__ float smp[4][32][33];
    __shared__ float part[4];
    const int w = threadIdx.x >> 5, lane = threadIdx.x & 31;

    float v[32];
    #pragma unroll
    for (int i = 0; i < 32; i++)
        v[i] = g_hist[w * NBINS2 + i * NB + lane];   // column 'lane'

    float cs = 0.0f;
    #pragma unroll
    for (int i = 0; i < 32; i++) cs += v[i];
    float norm = cs;
    #pragma unroll
    for (int o = 16; o > 0; o >>= 1) norm += __shfl_xor_sync(0xffffffffu, norm, o);
    float inv = __frcp_rn(norm);

    float ej = 0.0f;
    #pragma unroll
    for (int i = 0; i < 32; i++) {
        float p = v[i] * inv;
        smp[w][i][lane] = p;
        ej += p * __logf(p + EPS);
    }
    #pragma unroll
    for (int o = 16; o > 0; o >>= 1) ej += __shfl_xor_sync(0xffffffffu, ej, o);

    float q = cs * inv;
    float es = q * __logf(q + EPS);
    #pragma unroll
    for (int o = 16; o > 0; o >>= 1) es += __shfl_xor_sync(0xffffffffu, es, o);

    __syncwarp();
    float r = 0.0f;
    #pragma unroll
    for (int j = 0; j < 32; j++) r += smp[w][lane][j];
    float et = r * __logf(r + EPS);
    #pragma unroll
    for (int o = 16; o > 0; o >>= 1) et += __shfl_xor_sync(0xffffffffu, et, o);

    if (lane == 0) part[w] = (et + es) / ej;
    __syncthreads();
    if (threadIdx.x == 0)
        out[0] = -(part[0] + part[1] + part[2] + part[3]) * 0.25f;
}

// ---------------------------------------------------------------------------
extern "C" void kernel_launch(void* const* d_in, const int* in_sizes, int n_in,
                              void* d_out, int out_size) {
    const float* tar = (const float*)d_in[0];
    const float* src = (const float*)d_in[1];
    float* out = (float*)d_out;

    static bool attr_set = false;
    if (!attr_set) {
        cudaFuncSetAttribute(k_hist, cudaFuncAttributeMaxDynamicSharedMemorySize,
                             NBINS2 * 32 * sizeof(float));
        attr_set = true;
    }

    k_pre<<<dim3(MM_CTAS, NSAMP), 1024>>>(tar, src);
    k_hist<<<dim3(37, NSAMP), 1024, NBINS2 * 32 * sizeof(float)>>>(tar, src);
    k_final<<<1, 128>>>(out);
}

// round 8
// speedup vs baseline: 1.2691x; 1.0576x over previous
#include <cuda_runtime.h>

// ---------------------------------------------------------------------------
#define P_ELEMS (96*96*96)          // 884736 points per sample
#define NSAMP   4
#define NB      32
#define NBINS2  (NB*NB)
#define MM_CTAS 74                  // minmax CTAs per sample (74*4=296, 2/SM)
#define H_CTAS  37                  // hist CTAs per sample (37*4=148, 1/SM)

// C = 2048/961 = 2.1311134235 ; exp2 form: C*log2(e)
#define EXP2_C   3.0745468f
#define EXP2_2C  6.1490936f
#define G_1      0.11870463f        // exp(-C)
#define EPS      1e-10f

// ---------------------------------------------------------------------------
// Device scratch (no allocations allowed)
__device__ float    g_pmnT[NSAMP*MM_CTAS];
__device__ float    g_pmxT[NSAMP*MM_CTAS];
__device__ float    g_pmnS[NSAMP*MM_CTAS];
__device__ float    g_pmxS[NSAMP*MM_CTAS];
__device__ float    g_hist[NSAMP*NBINS2];
__device__ unsigned g_tick = 0;     // hist completion ticket

// ---------------------------------------------------------------------------
// Pass 1: per-CTA min/max partials. 2 CTAs/SM for latency hiding.
__global__ void __launch_bounds__(1024) k_pre(const float* __restrict__ tar,
                                              const float* __restrict__ src) {
    int b = blockIdx.y;
    if (b == 0) {
        int idx = blockIdx.x * 1024 + threadIdx.x;
        if (idx < NSAMP * NBINS2) g_hist[idx] = 0.0f;
    }

    const float4* t4 = (const float4*)(tar + (size_t)b * P_ELEMS);
    const float4* s4 = (const float4*)(src + (size_t)b * P_ELEMS);
    const int n4 = P_ELEMS / 4;                 // 221184
    const int stride = MM_CTAS * 1024;          // 75776

    float mnT = 1e30f, mxT = -1e30f, mnS = 1e30f, mxS = -1e30f;
    for (int i = blockIdx.x * 1024 + threadIdx.x; i < n4; i += stride) {
        float4 v = t4[i];
        float4 u = s4[i];
        mnT = fminf(mnT, fminf(fminf(v.x, v.y), fminf(v.z, v.w)));
        mxT = fmaxf(mxT, fmaxf(fmaxf(v.x, v.y), fmaxf(v.z, v.w)));
        mnS = fminf(mnS, fminf(fminf(u.x, u.y), fminf(u.z, u.w)));
        mxS = fmaxf(mxS, fmaxf(fmaxf(u.x, u.y), fmaxf(u.z, u.w)));
    }
    #pragma unroll
    for (int o = 16; o > 0; o >>= 1) {
        mnT = fminf(mnT, __shfl_xor_sync(0xffffffffu, mnT, o));
        mxT = fmaxf(mxT, __shfl_xor_sync(0xffffffffu, mxT, o));
        mnS = fminf(mnS, __shfl_xor_sync(0xffffffffu, mnS, o));
        mxS = fmaxf(mxS, __shfl_xor_sync(0xffffffffu, mxS, o));
    }
    __shared__ float sm[4][32];
    int w = threadIdx.x >> 5;
    if ((threadIdx.x & 31) == 0) {
        sm[0][w] = mnT; sm[1][w] = mxT; sm[2][w] = mnS; sm[3][w] = mxS;
    }
    __syncthreads();
    if (threadIdx.x == 0) {
        float a = sm[0][0], c = sm[1][0], e = sm[2][0], f = sm[3][0];
        #pragma unroll
        for (int k = 1; k < 32; k++) {
            a = fminf(a, sm[0][k]); c = fmaxf(c, sm[1][k]);
            e = fminf(e, sm[2][k]); f = fmaxf(f, sm[3][k]);
        }
        int slot = b * MM_CTAS + blockIdx.x;
        g_pmnT[slot] = a; g_pmxT[slot] = c;
        g_pmnS[slot] = e; g_pmxS[slot] = f;
    }
}

// ---------------------------------------------------------------------------
// 3-wide Gaussian window (ratio chain, 3 EX2). bins i0..i0+2, m = f-(i0+1).
__device__ __forceinline__ void gauss3(float f, int& i0, float w[3]) {
    i0 = min(max(__float2int_rn(f) - 1, 0), NB - 3);
    float m  = f - (float)i0 - 1.0f;
    float E  = exp2f(-EXP2_C * m * m);
    float X  = exp2f(-EXP2_2C * m);      // exp(-2Cm)
    float Xi = exp2f( EXP2_2C * m);      // exp(+2Cm)
    w[1] = E;
    float a = E * G_1;
    w[0] = a * X;                         // d = m+1
    w[2] = a * Xi;                        // d = m-1
}

// ---------------------------------------------------------------------------
// Pass 2: joint histogram (3x3 window, 9 conflict-free lane-ATOMS per point)
// + fused last-CTA finalize (norm, entropies, loss).
__global__ void __launch_bounds__(1024, 1) k_hist(const float* __restrict__ tar,
                                                  const float* __restrict__ src,
                                                  float* __restrict__ out) {
    extern __shared__ float sh[];           // [NBINS2][32] lane-interleaved
    const int b = blockIdx.y;
    const int tid = threadIdx.x;
    const int lane = tid & 31;

    float4* z4 = (float4*)sh;
    #pragma unroll
    for (int i = tid; i < NBINS2 * 32 / 4; i += 1024)
        z4[i] = make_float4(0.f, 0.f, 0.f, 0.f);

    __shared__ float lim[4];
    if (tid < 4) {
        const float* arr = (tid == 0) ? g_pmnT : (tid == 1) ? g_pmxT :
                           (tid == 2) ? g_pmnS : g_pmxS;
        bool ismin = (tid & 1) == 0;
        float r = __ldcg(&arr[b * MM_CTAS]);
        #pragma unroll 8
        for (int i = 1; i < MM_CTAS; i++) {
            float v = __ldcg(&arr[b * MM_CTAS + i]);
            r = ismin ? fminf(r, v) : fmaxf(r, v);
        }
        lim[tid] = r;
    }
    __syncthreads();

    const float mnT = lim[0], mxT = lim[1], mnS = lim[2], mxS = lim[3];
    const float scT = 31.0f / (mxT - mnT + 1e-12f);
    const float scS = 31.0f / (mxS - mnS + 1e-12f);

    const float4* t4 = (const float4*)(tar + (size_t)b * P_ELEMS);
    const float4* s4 = (const float4*)(src + (size_t)b * P_ELEMS);
    float* hb = sh + lane;
    const int n4 = P_ELEMS / 4;

    for (int p = blockIdx.x * 1024 + tid; p < n4; p += H_CTAS * 1024) {
        float4 tv = t4[p];
        float4 sv = s4[p];
        float tf[4] = {tv.x, tv.y, tv.z, tv.w};
        float sf[4] = {sv.x, sv.y, sv.z, sv.w};
        #pragma unroll
        for (int q = 0; q < 4; q++) {
            float ft = (tf[q] - mnT) * scT;
            float fs = (sf[q] - mnS) * scS;
            int it0, js0;
            float wt[3], ws[3];
            gauss3(ft, it0, wt);
            gauss3(fs, js0, ws);

            float* base = hb + ((it0 * NB + js0) << 5);
            #pragma unroll
            for (int k = 0; k < 3; k++) {
                float w = wt[k];
                #pragma unroll
                for (int l = 0; l < 3; l++)
                    atomicAdd(base + (((k * NB) + l) << 5), w * ws[l]);
            }
        }
    }

    __syncthreads();
    // merge 32 lane copies per bin (rotated, conflict-free), one bin per thread
    {
        const float* c = sh + (tid << 5);
        float s = 0.0f;
        #pragma unroll
        for (int i = 0; i < 32; i++) s += c[(lane + i) & 31];
        atomicAdd(&g_hist[b * NBINS2 + tid], s);
    }
    __threadfence();
    __syncthreads();

    // ---- last-CTA finalize (completion ticket, whole-CTA uniform branch) ----
    __shared__ unsigned s_rank;
    if (tid == 0) s_rank = atomicAdd(&g_tick, 1u);
    __syncthreads();

    if (s_rank == H_CTAS * NSAMP - 1) {
        float (*smp)[33] = (float(*)[33])sh;     // reuse smem: [4*32][33]
        __shared__ float part[4];

        if (tid < 128) {
            const int w = tid >> 5, ln = tid & 31;

            float v[32];
            #pragma unroll
            for (int i = 0; i < 32; i++)
                v[i] = __ldcg(&g_hist[w * NBINS2 + i * NB + ln]);  // column 'ln'

            float cs = 0.0f;
            #pragma unroll
            for (int i = 0; i < 32; i++) cs += v[i];
            float norm = cs;
            #pragma unroll
            for (int o = 16; o > 0; o >>= 1)
                norm += __shfl_xor_sync(0xffffffffu, norm, o);
            float inv = __frcp_rn(norm);

            float ej = 0.0f;
            #pragma unroll
            for (int i = 0; i < 32; i++) {
                float p = v[i] * inv;
                smp[w * 32 + i][ln] = p;
                ej += p * __logf(p + EPS);
            }
            #pragma unroll
            for (int o = 16; o > 0; o >>= 1)
                ej += __shfl_xor_sync(0xffffffffu, ej, o);

            float q = cs * inv;
            float es = q * __logf(q + EPS);
            #pragma unroll
            for (int o = 16; o > 0; o >>= 1)
                es += __shfl_xor_sync(0xffffffffu, es, o);

            __syncwarp();
            float r = 0.0f;
            #pragma unroll
            for (int j = 0; j < 32; j++) r += smp[w * 32 + ln][j];
            float et = r * __logf(r + EPS);
            #pragma unroll
            for (int o = 16; o > 0; o >>= 1)
                et += __shfl_xor_sync(0xffffffffu, et, o);

            if (ln == 0) part[w] = (et + es) / ej;
        }
        // REAL block barrier between part[] writes (warps 0-3) and the read
        // by thread 0. All 1024 threads of this CTA reach it (uniform branch).
        __syncthreads();
        if (tid == 0) {
            out[0] = -(part[0] + part[1] + part[2] + part[3]) * 0.25f;
            g_tick = 0u;            // reset for next graph replay
        }
    }
}

// ---------------------------------------------------------------------------
extern "C" void kernel_launch(void* const* d_in, const int* in_sizes, int n_in,
                              void* d_out, int out_size) {
    const float* tar = (const float*)d_in[0];
    const float* src = (const float*)d_in[1];
    float* out = (float*)d_out;

    static bool attr_set = false;
    if (!attr_set) {
        cudaFuncSetAttribute(k_hist, cudaFuncAttributeMaxDynamicSharedMemorySize,
                             NBINS2 * 32 * sizeof(float));
        attr_set = true;
    }

    k_pre<<<dim3(MM_CTAS, NSAMP), 1024>>>(tar, src);
    k_hist<<<dim3(H_CTAS, NSAMP), 1024, NBINS2 * 32 * sizeof(float)>>>(tar, src, out);
}

// round 9
// speedup vs baseline: 1.4358x; 1.1314x over previous
#include <cuda_runtime.h>

// ---------------------------------------------------------------------------
#define P_ELEMS (96*96*96)          // 884736 points per sample
#define NSAMP   4
#define NB      32
#define NBINS2  (NB*NB)
#define MM_CTAS 74                  // minmax CTAs per sample (74*4=296, 2/SM)
#define H_CTAS  37                  // hist CTAs per sample (37*4=148, 1/SM)

// C = 2048/961 = 2.1311134235 ; exp2 form: C*log2(e)
#define EXP2_C   3.0745468f
#define EXP2_2C  6.1490936f
#define G_1      0.11870463f        // exp(-C)
#define EPS      1e-10f

// ---------------------------------------------------------------------------
// Device scratch (no allocations allowed)
__device__ float    g_pmnT[NSAMP*MM_CTAS];
__device__ float    g_pmxT[NSAMP*MM_CTAS];
__device__ float    g_pmnS[NSAMP*MM_CTAS];
__device__ float    g_pmxS[NSAMP*MM_CTAS];
__device__ float    g_hist[NSAMP*NBINS2];
__device__ unsigned g_tick = 0;     // hist completion ticket

// ---------------------------------------------------------------------------
// Pass 1: per-CTA min/max partials. 2 CTAs/SM, 4 independent LDG.128 batched.
__global__ void __launch_bounds__(1024) k_pre(const float* __restrict__ tar,
                                              const float* __restrict__ src) {
    int b = blockIdx.y;
    if (b == 0) {
        int idx = blockIdx.x * 1024 + threadIdx.x;
        if (idx < NSAMP * NBINS2) g_hist[idx] = 0.0f;
    }

    const float4* t4 = (const float4*)(tar + (size_t)b * P_ELEMS);
    const float4* s4 = (const float4*)(src + (size_t)b * P_ELEMS);
    const int n4 = P_ELEMS / 4;                 // 221184
    const int stride = MM_CTAS * 1024;          // 75776

    const int i = blockIdx.x * 1024 + threadIdx.x;
    // every thread has >= 2 iterations (2*stride = 151552 < n4)
    float4 a0 = t4[i],          c0 = s4[i];
    float4 a1 = t4[i + stride], c1 = s4[i + stride];

    float mnT = fminf(fminf(fminf(a0.x, a0.y), fminf(a0.z, a0.w)),
                      fminf(fminf(a1.x, a1.y), fminf(a1.z, a1.w)));
    float mxT = fmaxf(fmaxf(fmaxf(a0.x, a0.y), fmaxf(a0.z, a0.w)),
                      fmaxf(fmaxf(a1.x, a1.y), fmaxf(a1.z, a1.w)));
    float mnS = fminf(fminf(fminf(c0.x, c0.y), fminf(c0.z, c0.w)),
                      fminf(fminf(c1.x, c1.y), fminf(c1.z, c1.w)));
    float mxS = fmaxf(fmaxf(fmaxf(c0.x, c0.y), fmaxf(c0.z, c0.w)),
                      fmaxf(fmaxf(c1.x, c1.y), fmaxf(c1.z, c1.w)));

    const int i2 = i + 2 * stride;
    if (i2 < n4) {
        float4 a2 = t4[i2], c2 = s4[i2];
        mnT = fminf(mnT, fminf(fminf(a2.x, a2.y), fminf(a2.z, a2.w)));
        mxT = fmaxf(mxT, fmaxf(fmaxf(a2.x, a2.y), fmaxf(a2.z, a2.w)));
        mnS = fminf(mnS, fminf(fminf(c2.x, c2.y), fminf(c2.z, c2.w)));
        mxS = fmaxf(mxS, fmaxf(fmaxf(c2.x, c2.y), fmaxf(c2.z, c2.w)));
    }

    #pragma unroll
    for (int o = 16; o > 0; o >>= 1) {
        mnT = fminf(mnT, __shfl_xor_sync(0xffffffffu, mnT, o));
        mxT = fmaxf(mxT, __shfl_xor_sync(0xffffffffu, mxT, o));
        mnS = fminf(mnS, __shfl_xor_sync(0xffffffffu, mnS, o));
        mxS = fmaxf(mxS, __shfl_xor_sync(0xffffffffu, mxS, o));
    }
    __shared__ float sm[4][32];
    int w = threadIdx.x >> 5;
    if ((threadIdx.x & 31) == 0) {
        sm[0][w] = mnT; sm[1][w] = mxT; sm[2][w] = mnS; sm[3][w] = mxS;
    }
    __syncthreads();
    if (threadIdx.x == 0) {
        float a = sm[0][0], c = sm[1][0], e = sm[2][0], f = sm[3][0];
        #pragma unroll
        for (int k = 1; k < 32; k++) {
            a = fminf(a, sm[0][k]); c = fmaxf(c, sm[1][k]);
            e = fminf(e, sm[2][k]); f = fmaxf(f, sm[3][k]);
        }
        int slot = b * MM_CTAS + blockIdx.x;
        g_pmnT[slot] = a; g_pmxT[slot] = c;
        g_pmnS[slot] = e; g_pmxS[slot] = f;
    }
}

// ---------------------------------------------------------------------------
// 3-wide Gaussian window (ratio chain, 3 EX2). Float-domain clamp.
__device__ __forceinline__ void gauss3(float f, int& i0, float w[3]) {
    float i0f = fminf(fmaxf(rintf(f) - 1.0f, 0.0f), (float)(NB - 3));
    i0 = (int)i0f;
    float m  = f - i0f - 1.0f;           // in [-0.5, 0.5] interior
    float E  = exp2f(-EXP2_C * m * m);
    float X  = exp2f(-EXP2_2C * m);
    float Xi = exp2f( EXP2_2C * m);
    w[1] = E;
    float a = E * G_1;
    w[0] = a * X;
    w[2] = a * Xi;
}

// 2-wide Gaussian window: bins i0, i0+1; m = f - i0 in [0,1) interior.
__device__ __forceinline__ void gauss2(float f, int& i0, float w[2]) {
    float i0f = fminf(fmaxf(floorf(f), 0.0f), (float)(NB - 2));
    i0 = (int)i0f;
    float m  = f - i0f;
    float m1 = 1.0f - m;
    w[0] = exp2f(-EXP2_C * m  * m);
    w[1] = exp2f(-EXP2_C * m1 * m1);
}

// ---------------------------------------------------------------------------
// Pass 2: joint histogram (3x2 window, 6 conflict-free lane-ATOMS per point)
// + fused last-CTA finalize.
__global__ void __launch_bounds__(1024, 1) k_hist(const float* __restrict__ tar,
                                                  const float* __restrict__ src,
                                                  float* __restrict__ out) {
    extern __shared__ float sh[];           // [NBINS2][32] lane-interleaved
    const int b = blockIdx.y;
    const int tid = threadIdx.x;
    const int lane = tid & 31;

    float4* z4 = (float4*)sh;
    #pragma unroll
    for (int i = tid; i < NBINS2 * 32 / 4; i += 1024)
        z4[i] = make_float4(0.f, 0.f, 0.f, 0.f);

    __shared__ float lim[4];
    if (tid < 4) {
        const float* arr = (tid == 0) ? g_pmnT : (tid == 1) ? g_pmxT :
                           (tid == 2) ? g_pmnS : g_pmxS;
        bool ismin = (tid & 1) == 0;
        float r = __ldcg(&arr[b * MM_CTAS]);
        #pragma unroll 8
        for (int i = 1; i < MM_CTAS; i++) {
            float v = __ldcg(&arr[b * MM_CTAS + i]);
            r = ismin ? fminf(r, v) : fmaxf(r, v);
        }
        lim[tid] = r;
    }
    __syncthreads();

    const float mnT = lim[0], mxT = lim[1], mnS = lim[2], mxS = lim[3];
    const float scT = 31.0f / (mxT - mnT + 1e-12f);
    const float scS = 31.0f / (mxS - mnS + 1e-12f);

    const float4* t4 = (const float4*)(tar + (size_t)b * P_ELEMS);
    const float4* s4 = (const float4*)(src + (size_t)b * P_ELEMS);
    float* hb = sh + lane;
    const int n4 = P_ELEMS / 4;

    for (int p = blockIdx.x * 1024 + tid; p < n4; p += H_CTAS * 1024) {
        float4 tv = t4[p];
        float4 sv = s4[p];
        float tf[4] = {tv.x, tv.y, tv.z, tv.w};
        float sf[4] = {sv.x, sv.y, sv.z, sv.w};
        #pragma unroll
        for (int q = 0; q < 4; q++) {
            float ft = (tf[q] - mnT) * scT;
            float fs = (sf[q] - mnS) * scS;
            int it0, js0;
            float wt[3], ws[2];
            gauss3(ft, it0, wt);
            gauss2(fs, js0, ws);

            float* base = hb + ((it0 * NB + js0) << 5);
            #pragma unroll
            for (int k = 0; k < 3; k++) {
                float w = wt[k];
                #pragma unroll
                for (int l = 0; l < 2; l++)
                    atomicAdd(base + (((k * NB) + l) << 5), w * ws[l]);
            }
        }
    }

    __syncthreads();
    // merge 32 lane copies per bin (rotated, conflict-free), one bin per thread
    {
        const float* c = sh + (tid << 5);
        float s = 0.0f;
        #pragma unroll
        for (int i = 0; i < 32; i++) s += c[(lane + i) & 31];
        atomicAdd(&g_hist[b * NBINS2 + tid], s);
    }
    __threadfence();
    __syncthreads();

    // ---- last-CTA finalize (completion ticket, whole-CTA uniform branch) ----
    __shared__ unsigned s_rank;
    if (tid == 0) s_rank = atomicAdd(&g_tick, 1u);
    __syncthreads();

    if (s_rank == H_CTAS * NSAMP - 1) {
        float (*smp)[33] = (float(*)[33])sh;     // reuse smem: [4*32][33]
        __shared__ float part[4];

        if (tid < 128) {
            const int w = tid >> 5, ln = tid & 31;

            float v[32];
            #pragma unroll
            for (int i = 0; i < 32; i++)
                v[i] = __ldcg(&g_hist[w * NBINS2 + i * NB + ln]);  // column 'ln'

            float cs = 0.0f;
            #pragma unroll
            for (int i = 0; i < 32; i++) cs += v[i];
            float norm = cs;
            #pragma unroll
            for (int o = 16; o > 0; o >>= 1)
                norm += __shfl_xor_sync(0xffffffffu, norm, o);
            float inv = __frcp_rn(norm);

            float ej = 0.0f;
            #pragma unroll
            for (int i = 0; i < 32; i++) {
                float p = v[i] * inv;
                smp[w * 32 + i][ln] = p;
                ej += p * __logf(p + EPS);
            }
            #pragma unroll
            for (int o = 16; o > 0; o >>= 1)
                ej += __shfl_xor_sync(0xffffffffu, ej, o);

            float q = cs * inv;
            float es = q * __logf(q + EPS);
            #pragma unroll
            for (int o = 16; o > 0; o >>= 1)
                es += __shfl_xor_sync(0xffffffffu, es, o);

            __syncwarp();
            float r = 0.0f;
            #pragma unroll
            for (int j = 0; j < 32; j++) r += smp[w * 32 + ln][j];
            float et = r * __logf(r + EPS);
            #pragma unroll
            for (int o = 16; o > 0; o >>= 1)
                et += __shfl_xor_sync(0xffffffffu, et, o);

            if (ln == 0) part[w] = (et + es) / ej;
        }
        __syncthreads();     // real block barrier before thread 0 reads part[]
        if (tid == 0) {
            out[0] = -(part[0] + part[1] + part[2] + part[3]) * 0.25f;
            g_tick = 0u;            // reset for next graph replay
        }
    }
}

// ---------------------------------------------------------------------------
extern "C" void kernel_launch(void* const* d_in, const int* in_sizes, int n_in,
                              void* d_out, int out_size) {
    const float* tar = (const float*)d_in[0];
    const float* src = (const float*)d_in[1];
    float* out = (float*)d_out;

    static bool attr_set = false;
    if (!attr_set) {
        cudaFuncSetAttribute(k_hist, cudaFuncAttributeMaxDynamicSharedMemorySize,
                             NBINS2 * 32 * sizeof(float));
        attr_set = true;
    }

    k_pre<<<dim3(MM_CTAS, NSAMP), 1024>>>(tar, src);
    k_hist<<<dim3(H_CTAS, NSAMP), 1024, NBINS2 * 32 * sizeof(float)>>>(tar, src, out);
}